// round 10
// baseline (speedup 1.0000x reference)
#include <cuda_runtime.h>

// Problem constants
#define BB  4
#define NN  2048
#define DD  512
#define HH  8
#define HDD 64
#define SCALE_F 0.044194173824159216f   // 512^-0.5

// Scratch (device globals; no allocation allowed)
static __device__ float g_Q[BB * HH * NN * HDD];
static __device__ float g_K[BB * HH * NN * HDD];
static __device__ float g_V[BB * HH * NN * HDD];
static __device__ float g_AO[BB * NN * DD];   // attention output, [B,N,D] row-major

// ---------------------------------------------------------------------------
// Kernel 1: QKV GEMM.  C[8192,1536] = X[8192,512] @ Wqkv[512,1536]
// 128x128 block tile, BK=16, 256 threads, 8x8 micro-tile.
// Epilogue scatters into g_Q/g_K/g_V with [B,H,N,HD] layout.
// ---------------------------------------------------------------------------
__global__ __launch_bounds__(256, 2)
void qkv_gemm(const float* __restrict__ X, const float* __restrict__ W) {
    __shared__ float As[16 * 132];   // transposed A tile [k][m], pad 132
    __shared__ float Bs[16 * 128];   // B tile [k][n]

    const int K  = DD;
    const int NC = 3 * DD;
    const int rowBase = blockIdx.y * 128;
    const int colBase = blockIdx.x * 128;
    const int t  = threadIdx.x;
    const int ty = t >> 4;
    const int tx = t & 15;

    float acc[8][8];
#pragma unroll
    for (int i = 0; i < 8; i++)
#pragma unroll
        for (int j = 0; j < 8; j++) acc[i][j] = 0.f;

    for (int kt = 0; kt < K; kt += 16) {
#pragma unroll
        for (int it = 0; it < 2; it++) {
            int idx = it * 256 + t;
            // A: 128 rows x 16 k  (4 float4 per row)
            int ra = idx >> 2;
            int ca = (idx & 3) << 2;
            float4 av = *(const float4*)&X[(rowBase + ra) * K + kt + ca];
            As[(ca + 0) * 132 + ra] = av.x;
            As[(ca + 1) * 132 + ra] = av.y;
            As[(ca + 2) * 132 + ra] = av.z;
            As[(ca + 3) * 132 + ra] = av.w;
            // B: 16 rows x 128 cols (32 float4 per row)
            int rb = idx >> 5;
            int cb = (idx & 31) << 2;
            *(float4*)&Bs[rb * 128 + cb] =
                *(const float4*)&W[(kt + rb) * NC + colBase + cb];
        }
        __syncthreads();

#pragma unroll
        for (int kk = 0; kk < 16; kk++) {
            float a[8], b[8];
            *(float4*)&a[0] = *(const float4*)&As[kk * 132 + ty * 8];
            *(float4*)&a[4] = *(const float4*)&As[kk * 132 + ty * 8 + 4];
            *(float4*)&b[0] = *(const float4*)&Bs[kk * 128 + tx * 8];
            *(float4*)&b[4] = *(const float4*)&Bs[kk * 128 + tx * 8 + 4];
#pragma unroll
            for (int i = 0; i < 8; i++)
#pragma unroll
                for (int j = 0; j < 8; j++) acc[i][j] += a[i] * b[j];
        }
        __syncthreads();
    }

    // Scatter epilogue. A 128-col tile lives entirely in one of {Q,K,V}
    // (1536 = 3*512, 512 % 128 == 0). The 8 cols per thread stay in one head.
    const int tsel = colBase >> 9;                 // 0:Q 1:K 2:V
    float* dst = (tsel == 0) ? g_Q : ((tsel == 1) ? g_K : g_V);
    const int cc = (colBase & 511) + tx * 8;       // col within the 512 block
    const int h  = cc >> 6;
    const int d0 = cc & 63;
#pragma unroll
    for (int i = 0; i < 8; i++) {
        int m = rowBase + ty * 8 + i;
        int b = m >> 11;
        int n = m & 2047;
        float* p = &dst[((b * HH + h) * NN + n) * HDD + d0];
        *(float4*)(p)     = make_float4(acc[i][0], acc[i][1], acc[i][2], acc[i][3]);
        *(float4*)(p + 4) = make_float4(acc[i][4], acc[i][5], acc[i][6], acc[i][7]);
    }
}

// ---------------------------------------------------------------------------
// Kernel 2: flash attention.  Block = (32 queries) x (one b,h).
// KV tiles of 64; online softmax; S tile overlaid into K-tile smem.
// ---------------------------------------------------------------------------
__global__ __launch_bounds__(256)
void attn_kernel() {
    __shared__ float Qs[32 * 64];     // [q][d]
    __shared__ float Kt[64 * 68];     // [d][k] pad 68; overlaid by Ss[q*65+k]
    __shared__ float Vs[64 * 64];     // [k][d]
    __shared__ float red[8 * 32];
    __shared__ float sm_m[32], sm_l[32], sm_c[32];

    const int qt = blockIdx.x;        // 0..63
    const int bh = blockIdx.y;        // 0..31
    const int t  = threadIdx.x;
    const int ty = t >> 4;            // 0..15 -> q micro rows (2)
    const int tx = t & 15;            // 0..15 -> k/d micro cols (4)
    const int rq = t & 31;            // reduction row
    const int rp = t >> 5;            // reduction part

    const float* Qg = g_Q + (bh * NN + qt * 32) * HDD;
    const float* Kg = g_K + bh * NN * HDD;
    const float* Vg = g_V + bh * NN * HDD;

#pragma unroll
    for (int it = 0; it < 2; it++) {
        int idx = it * 256 + t;
        int r = idx >> 4, c = (idx & 15) << 2;
        *(float4*)&Qs[r * 64 + c] = *(const float4*)&Qg[r * HDD + c];
    }
    if (t < 32) { sm_m[t] = -1e30f; sm_l[t] = 0.f; }

    float o[2][4];
#pragma unroll
    for (int i = 0; i < 2; i++)
#pragma unroll
        for (int j = 0; j < 4; j++) o[i][j] = 0.f;

    __syncthreads();

    for (int kv = 0; kv < NN; kv += 64) {
        // Load K (transposed into [d][k]) and V ([k][d]).
#pragma unroll
        for (int it = 0; it < 4; it++) {
            int idx = it * 256 + t;
            int r = idx >> 4, c = (idx & 15) << 2;
            float4 kvv = *(const float4*)&Kg[(kv + r) * HDD + c];
            Kt[(c + 0) * 68 + r] = kvv.x;
            Kt[(c + 1) * 68 + r] = kvv.y;
            Kt[(c + 2) * 68 + r] = kvv.z;
            Kt[(c + 3) * 68 + r] = kvv.w;
            *(float4*)&Vs[r * 64 + c] = *(const float4*)&Vg[(kv + r) * HDD + c];
        }
        __syncthreads();

        // S = Q K^T  (2x4 micro-tile per thread)
        float s[2][4];
#pragma unroll
        for (int i = 0; i < 2; i++)
#pragma unroll
            for (int j = 0; j < 4; j++) s[i][j] = 0.f;

#pragma unroll 16
        for (int d = 0; d < 64; d++) {
            float a0 = Qs[(ty * 2 + 0) * 64 + d];
            float a1 = Qs[(ty * 2 + 1) * 64 + d];
            float4 bb = *(const float4*)&Kt[d * 68 + tx * 4];
            s[0][0] += a0 * bb.x; s[0][1] += a0 * bb.y;
            s[0][2] += a0 * bb.z; s[0][3] += a0 * bb.w;
            s[1][0] += a1 * bb.x; s[1][1] += a1 * bb.y;
            s[1][2] += a1 * bb.z; s[1][3] += a1 * bb.w;
        }
        __syncthreads();              // all K reads done; Kt region reusable

        float* Ss = Kt;               // overlay: Ss[q*65 + k], 8320B <= 17408B
#pragma unroll
        for (int i = 0; i < 2; i++)
#pragma unroll
            for (int j = 0; j < 4; j++)
                Ss[(ty * 2 + i) * 65 + tx * 4 + j] = s[i][j] * SCALE_F;
        __syncthreads();

        // Row max (8 threads per row)
        float mx = Ss[rq * 65 + rp * 8];
#pragma unroll
        for (int kk = 1; kk < 8; kk++) mx = fmaxf(mx, Ss[rq * 65 + rp * 8 + kk]);
        red[rp * 32 + rq] = mx;
        __syncthreads();
        if (t < 32) {
            float m0 = red[t];
#pragma unroll
            for (int p = 1; p < 8; p++) m0 = fmaxf(m0, red[p * 32 + t]);
            float mo = sm_m[t];
            float mn = fmaxf(mo, m0);
            sm_c[t] = __expf(mo - mn);   // exp(-1e30)=0 on first tile
            sm_m[t] = mn;
        }
        __syncthreads();

        // exp + row sum
        float mq = sm_m[rq];
        float ssum = 0.f;
#pragma unroll
        for (int kk = 0; kk < 8; kk++) {
            float p = __expf(Ss[rq * 65 + rp * 8 + kk] - mq);
            Ss[rq * 65 + rp * 8 + kk] = p;
            ssum += p;
        }
        red[rp * 32 + rq] = ssum;
        __syncthreads();
        if (t < 32) {
            float s0 = red[t];
#pragma unroll
            for (int p = 1; p < 8; p++) s0 += red[p * 32 + t];
            sm_l[t] = sm_l[t] * sm_c[t] + s0;
        }

        // O = O*c + P V
        float c0 = sm_c[ty * 2 + 0];
        float c1 = sm_c[ty * 2 + 1];
#pragma unroll
        for (int j = 0; j < 4; j++) { o[0][j] *= c0; o[1][j] *= c1; }

#pragma unroll 8
        for (int k = 0; k < 64; k++) {
            float p0 = Ss[(ty * 2 + 0) * 65 + k];
            float p1 = Ss[(ty * 2 + 1) * 65 + k];
            float4 vv = *(const float4*)&Vs[k * 64 + tx * 4];
            o[0][0] += p0 * vv.x; o[0][1] += p0 * vv.y;
            o[0][2] += p0 * vv.z; o[0][3] += p0 * vv.w;
            o[1][0] += p1 * vv.x; o[1][1] += p1 * vv.y;
            o[1][2] += p1 * vv.z; o[1][3] += p1 * vv.w;
        }
        __syncthreads();              // before next tile overwrites Kt/Ss/Vs
    }

    const float il0 = 1.f / sm_l[ty * 2 + 0];
    const float il1 = 1.f / sm_l[ty * 2 + 1];
    const int b = bh >> 3, h = bh & 7;
    const int q0 = qt * 32 + ty * 2;
    float* dst = g_AO + (b * NN + q0) * DD + h * HDD + tx * 4;
    *(float4*)(dst)      = make_float4(o[0][0] * il0, o[0][1] * il0,
                                       o[0][2] * il0, o[0][3] * il0);
    *(float4*)(dst + DD) = make_float4(o[1][0] * il1, o[1][1] * il1,
                                       o[1][2] * il1, o[1][3] * il1);
}

// ---------------------------------------------------------------------------
// Kernel 3: out projection.  out[8192,512] = AO @ Wout + bias
// ---------------------------------------------------------------------------
__global__ __launch_bounds__(256, 2)
void out_gemm(const float* __restrict__ W, const float* __restrict__ bias,
              float* __restrict__ out) {
    __shared__ float As[16 * 132];
    __shared__ float Bs[16 * 128];

    const int K  = DD;
    const int NC = DD;
    const int rowBase = blockIdx.y * 128;
    const int colBase = blockIdx.x * 128;
    const int t  = threadIdx.x;
    const int ty = t >> 4;
    const int tx = t & 15;

    float acc[8][8];
#pragma unroll
    for (int i = 0; i < 8; i++)
#pragma unroll
        for (int j = 0; j < 8; j++) acc[i][j] = 0.f;

    for (int kt = 0; kt < K; kt += 16) {
#pragma unroll
        for (int it = 0; it < 2; it++) {
            int idx = it * 256 + t;
            int ra = idx >> 2;
            int ca = (idx & 3) << 2;
            float4 av = *(const float4*)&g_AO[(rowBase + ra) * K + kt + ca];
            As[(ca + 0) * 132 + ra] = av.x;
            As[(ca + 1) * 132 + ra] = av.y;
            As[(ca + 2) * 132 + ra] = av.z;
            As[(ca + 3) * 132 + ra] = av.w;
            int rb = idx >> 5;
            int cb = (idx & 31) << 2;
            *(float4*)&Bs[rb * 128 + cb] =
                *(const float4*)&W[(kt + rb) * NC + colBase + cb];
        }
        __syncthreads();

#pragma unroll
        for (int kk = 0; kk < 16; kk++) {
            float a[8], b[8];
            *(float4*)&a[0] = *(const float4*)&As[kk * 132 + ty * 8];
            *(float4*)&a[4] = *(const float4*)&As[kk * 132 + ty * 8 + 4];
            *(float4*)&b[0] = *(const float4*)&Bs[kk * 128 + tx * 8];
            *(float4*)&b[4] = *(const float4*)&Bs[kk * 128 + tx * 8 + 4];
#pragma unroll
            for (int i = 0; i < 8; i++)
#pragma unroll
                for (int j = 0; j < 8; j++) acc[i][j] += a[i] * b[j];
        }
        __syncthreads();
    }

    const int col = colBase + tx * 8;
    float4 bv0 = *(const float4*)&bias[col];
    float4 bv1 = *(const float4*)&bias[col + 4];
#pragma unroll
    for (int i = 0; i < 8; i++) {
        int m = rowBase + ty * 8 + i;
        float* p = &out[m * NC + col];
        *(float4*)(p)     = make_float4(acc[i][0] + bv0.x, acc[i][1] + bv0.y,
                                        acc[i][2] + bv0.z, acc[i][3] + bv0.w);
        *(float4*)(p + 4) = make_float4(acc[i][4] + bv1.x, acc[i][5] + bv1.y,
                                        acc[i][6] + bv1.z, acc[i][7] + bv1.w);
    }
}

// ---------------------------------------------------------------------------
extern "C" void kernel_launch(void* const* d_in, const int* in_sizes, int n_in,
                              void* d_out, int out_size) {
    const float* x     = (const float*)d_in[0];   // [4,2048,512]
    const float* w_qkv = (const float*)d_in[1];   // [512,1536]
    const float* w_out = (const float*)d_in[2];   // [512,512]
    const float* b_out = (const float*)d_in[3];   // [512]
    float* out = (float*)d_out;                   // [4,2048,512]

    qkv_gemm<<<dim3(12, 64), 256>>>(x, w_qkv);        // 1536/128 x 8192/128
    attn_kernel<<<dim3(64, 32), 256>>>();             // 2048/32 q-tiles x 32 bh
    out_gemm<<<dim3(4, 64), 256>>>(w_out, b_out, out);
}

// round 11
// speedup vs baseline: 1.0015x; 1.0015x over previous
#include <cuda_runtime.h>

// Problem constants
#define BB  4
#define NN  2048
#define DD  512
#define HH  8
#define HDD 64
#define SCALE_F 0.044194173824159216f   // 512^-0.5

// Scratch (device globals; no allocation allowed)
static __device__ float g_Q[BB * HH * NN * HDD];
static __device__ float g_K[BB * HH * NN * HDD];
static __device__ float g_V[BB * HH * NN * HDD];
static __device__ float g_AO[BB * NN * DD];   // attention output, [B,N,D] row-major

// ---------------------------------------------------------------------------
// Kernel 1: QKV GEMM.  C[8192,1536] = X[8192,512] @ Wqkv[512,1536]
// 128x128 block tile, BK=16, 256 threads, 8x8 micro-tile.
// Epilogue scatters into g_Q/g_K/g_V with [B,H,N,HD] layout.
// ---------------------------------------------------------------------------
__global__ __launch_bounds__(256, 2)
void qkv_gemm(const float* __restrict__ X, const float* __restrict__ W) {
    __shared__ float As[16 * 132];   // transposed A tile [k][m], pad 132
    __shared__ float Bs[16 * 128];   // B tile [k][n]

    const int K  = DD;
    const int NC = 3 * DD;
    const int rowBase = blockIdx.y * 128;
    const int colBase = blockIdx.x * 128;
    const int t  = threadIdx.x;
    const int ty = t >> 4;
    const int tx = t & 15;

    float acc[8][8];
#pragma unroll
    for (int i = 0; i < 8; i++)
#pragma unroll
        for (int j = 0; j < 8; j++) acc[i][j] = 0.f;

    for (int kt = 0; kt < K; kt += 16) {
#pragma unroll
        for (int it = 0; it < 2; it++) {
            int idx = it * 256 + t;
            // A: 128 rows x 16 k  (4 float4 per row)
            int ra = idx >> 2;
            int ca = (idx & 3) << 2;
            float4 av = *(const float4*)&X[(rowBase + ra) * K + kt + ca];
            As[(ca + 0) * 132 + ra] = av.x;
            As[(ca + 1) * 132 + ra] = av.y;
            As[(ca + 2) * 132 + ra] = av.z;
            As[(ca + 3) * 132 + ra] = av.w;
            // B: 16 rows x 128 cols (32 float4 per row)
            int rb = idx >> 5;
            int cb = (idx & 31) << 2;
            *(float4*)&Bs[rb * 128 + cb] =
                *(const float4*)&W[(kt + rb) * NC + colBase + cb];
        }
        __syncthreads();

#pragma unroll
        for (int kk = 0; kk < 16; kk++) {
            float a[8], b[8];
            *(float4*)&a[0] = *(const float4*)&As[kk * 132 + ty * 8];
            *(float4*)&a[4] = *(const float4*)&As[kk * 132 + ty * 8 + 4];
            *(float4*)&b[0] = *(const float4*)&Bs[kk * 128 + tx * 8];
            *(float4*)&b[4] = *(const float4*)&Bs[kk * 128 + tx * 8 + 4];
#pragma unroll
            for (int i = 0; i < 8; i++)
#pragma unroll
                for (int j = 0; j < 8; j++) acc[i][j] += a[i] * b[j];
        }
        __syncthreads();
    }

    // Scatter epilogue. A 128-col tile lives entirely in one of {Q,K,V}
    // (1536 = 3*512, 512 % 128 == 0). The 8 cols per thread stay in one head.
    const int tsel = colBase >> 9;                 // 0:Q 1:K 2:V
    float* dst = (tsel == 0) ? g_Q : ((tsel == 1) ? g_K : g_V);
    const int cc = (colBase & 511) + tx * 8;       // col within the 512 block
    const int h  = cc >> 6;
    const int d0 = cc & 63;
#pragma unroll
    for (int i = 0; i < 8; i++) {
        int m = rowBase + ty * 8 + i;
        int b = m >> 11;
        int n = m & 2047;
        float* p = &dst[((b * HH + h) * NN + n) * HDD + d0];
        *(float4*)(p)     = make_float4(acc[i][0], acc[i][1], acc[i][2], acc[i][3]);
        *(float4*)(p + 4) = make_float4(acc[i][4], acc[i][5], acc[i][6], acc[i][7]);
    }
}

// ---------------------------------------------------------------------------
// Kernel 2: flash attention.  Block = (32 queries) x (one b,h).
// KV tiles of 64; online softmax; S tile overlaid into K-tile smem.
// ---------------------------------------------------------------------------
__global__ __launch_bounds__(256)
void attn_kernel() {
    __shared__ float Qs[32 * 64];     // [q][d]
    __shared__ float Kt[64 * 68];     // [d][k] pad 68; overlaid by Ss[q*65+k]
    __shared__ float Vs[64 * 64];     // [k][d]
    __shared__ float red[8 * 32];
    __shared__ float sm_m[32], sm_l[32], sm_c[32];

    const int qt = blockIdx.x;        // 0..63
    const int bh = blockIdx.y;        // 0..31
    const int t  = threadIdx.x;
    const int ty = t >> 4;            // 0..15 -> q micro rows (2)
    const int tx = t & 15;            // 0..15 -> k/d micro cols (4)
    const int rq = t & 31;            // reduction row
    const int rp = t >> 5;            // reduction part

    const float* Qg = g_Q + (bh * NN + qt * 32) * HDD;
    const float* Kg = g_K + bh * NN * HDD;
    const float* Vg = g_V + bh * NN * HDD;

#pragma unroll
    for (int it = 0; it < 2; it++) {
        int idx = it * 256 + t;
        int r = idx >> 4, c = (idx & 15) << 2;
        *(float4*)&Qs[r * 64 + c] = *(const float4*)&Qg[r * HDD + c];
    }
    if (t < 32) { sm_m[t] = -1e30f; sm_l[t] = 0.f; }

    float o[2][4];
#pragma unroll
    for (int i = 0; i < 2; i++)
#pragma unroll
        for (int j = 0; j < 4; j++) o[i][j] = 0.f;

    __syncthreads();

    for (int kv = 0; kv < NN; kv += 64) {
        // Load K (transposed into [d][k]) and V ([k][d]).
#pragma unroll
        for (int it = 0; it < 4; it++) {
            int idx = it * 256 + t;
            int r = idx >> 4, c = (idx & 15) << 2;
            float4 kvv = *(const float4*)&Kg[(kv + r) * HDD + c];
            Kt[(c + 0) * 68 + r] = kvv.x;
            Kt[(c + 1) * 68 + r] = kvv.y;
            Kt[(c + 2) * 68 + r] = kvv.z;
            Kt[(c + 3) * 68 + r] = kvv.w;
            *(float4*)&Vs[r * 64 + c] = *(const float4*)&Vg[(kv + r) * HDD + c];
        }
        __syncthreads();

        // S = Q K^T  (2x4 micro-tile per thread)
        float s[2][4];
#pragma unroll
        for (int i = 0; i < 2; i++)
#pragma unroll
            for (int j = 0; j < 4; j++) s[i][j] = 0.f;

#pragma unroll 16
        for (int d = 0; d < 64; d++) {
            float a0 = Qs[(ty * 2 + 0) * 64 + d];
            float a1 = Qs[(ty * 2 + 1) * 64 + d];
            float4 bb = *(const float4*)&Kt[d * 68 + tx * 4];
            s[0][0] += a0 * bb.x; s[0][1] += a0 * bb.y;
            s[0][2] += a0 * bb.z; s[0][3] += a0 * bb.w;
            s[1][0] += a1 * bb.x; s[1][1] += a1 * bb.y;
            s[1][2] += a1 * bb.z; s[1][3] += a1 * bb.w;
        }
        __syncthreads();              // all K reads done; Kt region reusable

        float* Ss = Kt;               // overlay: Ss[q*65 + k], 8320B <= 17408B
#pragma unroll
        for (int i = 0; i < 2; i++)
#pragma unroll
            for (int j = 0; j < 4; j++)
                Ss[(ty * 2 + i) * 65 + tx * 4 + j] = s[i][j] * SCALE_F;
        __syncthreads();

        // Row max (8 threads per row)
        float mx = Ss[rq * 65 + rp * 8];
#pragma unroll
        for (int kk = 1; kk < 8; kk++) mx = fmaxf(mx, Ss[rq * 65 + rp * 8 + kk]);
        red[rp * 32 + rq] = mx;
        __syncthreads();
        if (t < 32) {
            float m0 = red[t];
#pragma unroll
            for (int p = 1; p < 8; p++) m0 = fmaxf(m0, red[p * 32 + t]);
            float mo = sm_m[t];
            float mn = fmaxf(mo, m0);
            sm_c[t] = __expf(mo - mn);   // exp(-1e30)=0 on first tile
            sm_m[t] = mn;
        }
        __syncthreads();

        // exp + row sum
        float mq = sm_m[rq];
        float ssum = 0.f;
#pragma unroll
        for (int kk = 0; kk < 8; kk++) {
            float p = __expf(Ss[rq * 65 + rp * 8 + kk] - mq);
            Ss[rq * 65 + rp * 8 + kk] = p;
            ssum += p;
        }
        red[rp * 32 + rq] = ssum;
        __syncthreads();
        if (t < 32) {
            float s0 = red[t];
#pragma unroll
            for (int p = 1; p < 8; p++) s0 += red[p * 32 + t];
            sm_l[t] = sm_l[t] * sm_c[t] + s0;
        }

        // O = O*c + P V
        float c0 = sm_c[ty * 2 + 0];
        float c1 = sm_c[ty * 2 + 1];
#pragma unroll
        for (int j = 0; j < 4; j++) { o[0][j] *= c0; o[1][j] *= c1; }

#pragma unroll 8
        for (int k = 0; k < 64; k++) {
            float p0 = Ss[(ty * 2 + 0) * 65 + k];
            float p1 = Ss[(ty * 2 + 1) * 65 + k];
            float4 vv = *(const float4*)&Vs[k * 64 + tx * 4];
            o[0][0] += p0 * vv.x; o[0][1] += p0 * vv.y;
            o[0][2] += p0 * vv.z; o[0][3] += p0 * vv.w;
            o[1][0] += p1 * vv.x; o[1][1] += p1 * vv.y;
            o[1][2] += p1 * vv.z; o[1][3] += p1 * vv.w;
        }
        __syncthreads();              // before next tile overwrites Kt/Ss/Vs
    }

    const float il0 = 1.f / sm_l[ty * 2 + 0];
    const float il1 = 1.f / sm_l[ty * 2 + 1];
    const int b = bh >> 3, h = bh & 7;
    const int q0 = qt * 32 + ty * 2;
    float* dst = g_AO + (b * NN + q0) * DD + h * HDD + tx * 4;
    *(float4*)(dst)      = make_float4(o[0][0] * il0, o[0][1] * il0,
                                       o[0][2] * il0, o[0][3] * il0);
    *(float4*)(dst + DD) = make_float4(o[1][0] * il1, o[1][1] * il1,
                                       o[1][2] * il1, o[1][3] * il1);
}

// ---------------------------------------------------------------------------
// Kernel 3: out projection.  out[8192,512] = AO @ Wout + bias
// ---------------------------------------------------------------------------
__global__ __launch_bounds__(256, 2)
void out_gemm(const float* __restrict__ W, const float* __restrict__ bias,
              float* __restrict__ out) {
    __shared__ float As[16 * 132];
    __shared__ float Bs[16 * 128];

    const int K  = DD;
    const int NC = DD;
    const int rowBase = blockIdx.y * 128;
    const int colBase = blockIdx.x * 128;
    const int t  = threadIdx.x;
    const int ty = t >> 4;
    const int tx = t & 15;

    float acc[8][8];
#pragma unroll
    for (int i = 0; i < 8; i++)
#pragma unroll
        for (int j = 0; j < 8; j++) acc[i][j] = 0.f;

    for (int kt = 0; kt < K; kt += 16) {
#pragma unroll
        for (int it = 0; it < 2; it++) {
            int idx = it * 256 + t;
            int ra = idx >> 2;
            int ca = (idx & 3) << 2;
            float4 av = *(const float4*)&g_AO[(rowBase + ra) * K + kt + ca];
            As[(ca + 0) * 132 + ra] = av.x;
            As[(ca + 1) * 132 + ra] = av.y;
            As[(ca + 2) * 132 + ra] = av.z;
            As[(ca + 3) * 132 + ra] = av.w;
            int rb = idx >> 5;
            int cb = (idx & 31) << 2;
            *(float4*)&Bs[rb * 128 + cb] =
                *(const float4*)&W[(kt + rb) * NC + colBase + cb];
        }
        __syncthreads();

#pragma unroll
        for (int kk = 0; kk < 16; kk++) {
            float a[8], b[8];
            *(float4*)&a[0] = *(const float4*)&As[kk * 132 + ty * 8];
            *(float4*)&a[4] = *(const float4*)&As[kk * 132 + ty * 8 + 4];
            *(float4*)&b[0] = *(const float4*)&Bs[kk * 128 + tx * 8];
            *(float4*)&b[4] = *(const float4*)&Bs[kk * 128 + tx * 8 + 4];
#pragma unroll
            for (int i = 0; i < 8; i++)
#pragma unroll
                for (int j = 0; j < 8; j++) acc[i][j] += a[i] * b[j];
        }
        __syncthreads();
    }

    const int col = colBase + tx * 8;
    float4 bv0 = *(const float4*)&bias[col];
    float4 bv1 = *(const float4*)&bias[col + 4];
#pragma unroll
    for (int i = 0; i < 8; i++) {
        int m = rowBase + ty * 8 + i;
        float* p = &out[m * NC + col];
        *(float4*)(p)     = make_float4(acc[i][0] + bv0.x, acc[i][1] + bv0.y,
                                        acc[i][2] + bv0.z, acc[i][3] + bv0.w);
        *(float4*)(p + 4) = make_float4(acc[i][4] + bv1.x, acc[i][5] + bv1.y,
                                        acc[i][6] + bv1.z, acc[i][7] + bv1.w);
    }
}

// ---------------------------------------------------------------------------
extern "C" void kernel_launch(void* const* d_in, const int* in_sizes, int n_in,
                              void* d_out, int out_size) {
    const float* x     = (const float*)d_in[0];   // [4,2048,512]
    const float* w_qkv = (const float*)d_in[1];   // [512,1536]
    const float* w_out = (const float*)d_in[2];   // [512,512]
    const float* b_out = (const float*)d_in[3];   // [512]
    float* out = (float*)d_out;                   // [4,2048,512]

    qkv_gemm<<<dim3(12, 64), 256>>>(x, w_qkv);        // 1536/128 x 8192/128
    attn_kernel<<<dim3(64, 32), 256>>>();             // 2048/32 q-tiles x 32 bh
    out_gemm<<<dim3(4, 64), 256>>>(w_out, b_out, out);
}

// round 12
// speedup vs baseline: 1.0018x; 1.0003x over previous
#include <cuda_runtime.h>

// Problem constants
#define BB  4
#define NN  2048
#define DD  512
#define HH  8
#define HDD 64
#define SCALE_F 0.044194173824159216f   // 512^-0.5

// Scratch (device globals; no allocation allowed)
static __device__ float g_Q[BB * HH * NN * HDD];
static __device__ float g_K[BB * HH * NN * HDD];
static __device__ float g_V[BB * HH * NN * HDD];
static __device__ float g_AO[BB * NN * DD];   // attention output, [B,N,D] row-major

// ---------------------------------------------------------------------------
// Kernel 1: QKV GEMM.  C[8192,1536] = X[8192,512] @ Wqkv[512,1536]
// 128x128 block tile, BK=16, 256 threads, 8x8 micro-tile.
// Epilogue scatters into g_Q/g_K/g_V with [B,H,N,HD] layout.
// ---------------------------------------------------------------------------
__global__ __launch_bounds__(256, 2)
void qkv_gemm(const float* __restrict__ X, const float* __restrict__ W) {
    __shared__ float As[16 * 132];   // transposed A tile [k][m], pad 132
    __shared__ float Bs[16 * 128];   // B tile [k][n]

    const int K  = DD;
    const int NC = 3 * DD;
    const int rowBase = blockIdx.y * 128;
    const int colBase = blockIdx.x * 128;
    const int t  = threadIdx.x;
    const int ty = t >> 4;
    const int tx = t & 15;

    float acc[8][8];
#pragma unroll
    for (int i = 0; i < 8; i++)
#pragma unroll
        for (int j = 0; j < 8; j++) acc[i][j] = 0.f;

    for (int kt = 0; kt < K; kt += 16) {
#pragma unroll
        for (int it = 0; it < 2; it++) {
            int idx = it * 256 + t;
            // A: 128 rows x 16 k  (4 float4 per row)
            int ra = idx >> 2;
            int ca = (idx & 3) << 2;
            float4 av = *(const float4*)&X[(rowBase + ra) * K + kt + ca];
            As[(ca + 0) * 132 + ra] = av.x;
            As[(ca + 1) * 132 + ra] = av.y;
            As[(ca + 2) * 132 + ra] = av.z;
            As[(ca + 3) * 132 + ra] = av.w;
            // B: 16 rows x 128 cols (32 float4 per row)
            int rb = idx >> 5;
            int cb = (idx & 31) << 2;
            *(float4*)&Bs[rb * 128 + cb] =
                *(const float4*)&W[(kt + rb) * NC + colBase + cb];
        }
        __syncthreads();

#pragma unroll
        for (int kk = 0; kk < 16; kk++) {
            float a[8], b[8];
            *(float4*)&a[0] = *(const float4*)&As[kk * 132 + ty * 8];
            *(float4*)&a[4] = *(const float4*)&As[kk * 132 + ty * 8 + 4];
            *(float4*)&b[0] = *(const float4*)&Bs[kk * 128 + tx * 8];
            *(float4*)&b[4] = *(const float4*)&Bs[kk * 128 + tx * 8 + 4];
#pragma unroll
            for (int i = 0; i < 8; i++)
#pragma unroll
                for (int j = 0; j < 8; j++) acc[i][j] += a[i] * b[j];
        }
        __syncthreads();
    }

    // Scatter epilogue. A 128-col tile lives entirely in one of {Q,K,V}
    // (1536 = 3*512, 512 % 128 == 0). The 8 cols per thread stay in one head.
    const int tsel = colBase >> 9;                 // 0:Q 1:K 2:V
    float* dst = (tsel == 0) ? g_Q : ((tsel == 1) ? g_K : g_V);
    const int cc = (colBase & 511) + tx * 8;       // col within the 512 block
    const int h  = cc >> 6;
    const int d0 = cc & 63;
#pragma unroll
    for (int i = 0; i < 8; i++) {
        int m = rowBase + ty * 8 + i;
        int b = m >> 11;
        int n = m & 2047;
        float* p = &dst[((b * HH + h) * NN + n) * HDD + d0];
        *(float4*)(p)     = make_float4(acc[i][0], acc[i][1], acc[i][2], acc[i][3]);
        *(float4*)(p + 4) = make_float4(acc[i][4], acc[i][5], acc[i][6], acc[i][7]);
    }
}

// ---------------------------------------------------------------------------
// Kernel 2: flash attention.  Block = (32 queries) x (one b,h).
// KV tiles of 64; online softmax; S tile overlaid into K-tile smem.
// ---------------------------------------------------------------------------
__global__ __launch_bounds__(256)
void attn_kernel() {
    __shared__ float Qs[32 * 64];     // [q][d]
    __shared__ float Kt[64 * 68];     // [d][k] pad 68; overlaid by Ss[q*65+k]
    __shared__ float Vs[64 * 64];     // [k][d]
    __shared__ float red[8 * 32];
    __shared__ float sm_m[32], sm_l[32], sm_c[32];

    const int qt = blockIdx.x;        // 0..63
    const int bh = blockIdx.y;        // 0..31
    const int t  = threadIdx.x;
    const int ty = t >> 4;            // 0..15 -> q micro rows (2)
    const int tx = t & 15;            // 0..15 -> k/d micro cols (4)
    const int rq = t & 31;            // reduction row
    const int rp = t >> 5;            // reduction part

    const float* Qg = g_Q + (bh * NN + qt * 32) * HDD;
    const float* Kg = g_K + bh * NN * HDD;
    const float* Vg = g_V + bh * NN * HDD;

#pragma unroll
    for (int it = 0; it < 2; it++) {
        int idx = it * 256 + t;
        int r = idx >> 4, c = (idx & 15) << 2;
        *(float4*)&Qs[r * 64 + c] = *(const float4*)&Qg[r * HDD + c];
    }
    if (t < 32) { sm_m[t] = -1e30f; sm_l[t] = 0.f; }

    float o[2][4];
#pragma unroll
    for (int i = 0; i < 2; i++)
#pragma unroll
        for (int j = 0; j < 4; j++) o[i][j] = 0.f;

    __syncthreads();

    for (int kv = 0; kv < NN; kv += 64) {
        // Load K (transposed into [d][k]) and V ([k][d]).
#pragma unroll
        for (int it = 0; it < 4; it++) {
            int idx = it * 256 + t;
            int r = idx >> 4, c = (idx & 15) << 2;
            float4 kvv = *(const float4*)&Kg[(kv + r) * HDD + c];
            Kt[(c + 0) * 68 + r] = kvv.x;
            Kt[(c + 1) * 68 + r] = kvv.y;
            Kt[(c + 2) * 68 + r] = kvv.z;
            Kt[(c + 3) * 68 + r] = kvv.w;
            *(float4*)&Vs[r * 64 + c] = *(const float4*)&Vg[(kv + r) * HDD + c];
        }
        __syncthreads();

        // S = Q K^T  (2x4 micro-tile per thread)
        float s[2][4];
#pragma unroll
        for (int i = 0; i < 2; i++)
#pragma unroll
            for (int j = 0; j < 4; j++) s[i][j] = 0.f;

#pragma unroll 16
        for (int d = 0; d < 64; d++) {
            float a0 = Qs[(ty * 2 + 0) * 64 + d];
            float a1 = Qs[(ty * 2 + 1) * 64 + d];
            float4 bb = *(const float4*)&Kt[d * 68 + tx * 4];
            s[0][0] += a0 * bb.x; s[0][1] += a0 * bb.y;
            s[0][2] += a0 * bb.z; s[0][3] += a0 * bb.w;
            s[1][0] += a1 * bb.x; s[1][1] += a1 * bb.y;
            s[1][2] += a1 * bb.z; s[1][3] += a1 * bb.w;
        }
        __syncthreads();              // all K reads done; Kt region reusable

        float* Ss = Kt;               // overlay: Ss[q*65 + k], 8320B <= 17408B
#pragma unroll
        for (int i = 0; i < 2; i++)
#pragma unroll
            for (int j = 0; j < 4; j++)
                Ss[(ty * 2 + i) * 65 + tx * 4 + j] = s[i][j] * SCALE_F;
        __syncthreads();

        // Row max (8 threads per row)
        float mx = Ss[rq * 65 + rp * 8];
#pragma unroll
        for (int kk = 1; kk < 8; kk++) mx = fmaxf(mx, Ss[rq * 65 + rp * 8 + kk]);
        red[rp * 32 + rq] = mx;
        __syncthreads();
        if (t < 32) {
            float m0 = red[t];
#pragma unroll
            for (int p = 1; p < 8; p++) m0 = fmaxf(m0, red[p * 32 + t]);
            float mo = sm_m[t];
            float mn = fmaxf(mo, m0);
            sm_c[t] = __expf(mo - mn);   // exp(-1e30)=0 on first tile
            sm_m[t] = mn;
        }
        __syncthreads();

        // exp + row sum
        float mq = sm_m[rq];
        float ssum = 0.f;
#pragma unroll
        for (int kk = 0; kk < 8; kk++) {
            float p = __expf(Ss[rq * 65 + rp * 8 + kk] - mq);
            Ss[rq * 65 + rp * 8 + kk] = p;
            ssum += p;
        }
        red[rp * 32 + rq] = ssum;
        __syncthreads();
        if (t < 32) {
            float s0 = red[t];
#pragma unroll
            for (int p = 1; p < 8; p++) s0 += red[p * 32 + t];
            sm_l[t] = sm_l[t] * sm_c[t] + s0;
        }

        // O = O*c + P V
        float c0 = sm_c[ty * 2 + 0];
        float c1 = sm_c[ty * 2 + 1];
#pragma unroll
        for (int j = 0; j < 4; j++) { o[0][j] *= c0; o[1][j] *= c1; }

#pragma unroll 8
        for (int k = 0; k < 64; k++) {
            float p0 = Ss[(ty * 2 + 0) * 65 + k];
            float p1 = Ss[(ty * 2 + 1) * 65 + k];
            float4 vv = *(const float4*)&Vs[k * 64 + tx * 4];
            o[0][0] += p0 * vv.x; o[0][1] += p0 * vv.y;
            o[0][2] += p0 * vv.z; o[0][3] += p0 * vv.w;
            o[1][0] += p1 * vv.x; o[1][1] += p1 * vv.y;
            o[1][2] += p1 * vv.z; o[1][3] += p1 * vv.w;
        }
        __syncthreads();              // before next tile overwrites Kt/Ss/Vs
    }

    const float il0 = 1.f / sm_l[ty * 2 + 0];
    const float il1 = 1.f / sm_l[ty * 2 + 1];
    const int b = bh >> 3, h = bh & 7;
    const int q0 = qt * 32 + ty * 2;
    float* dst = g_AO + (b * NN + q0) * DD + h * HDD + tx * 4;
    *(float4*)(dst)      = make_float4(o[0][0] * il0, o[0][1] * il0,
                                       o[0][2] * il0, o[0][3] * il0);
    *(float4*)(dst + DD) = make_float4(o[1][0] * il1, o[1][1] * il1,
                                       o[1][2] * il1, o[1][3] * il1);
}

// ---------------------------------------------------------------------------
// Kernel 3: out projection.  out[8192,512] = AO @ Wout + bias
// ---------------------------------------------------------------------------
__global__ __launch_bounds__(256, 2)
void out_gemm(const float* __restrict__ W, const float* __restrict__ bias,
              float* __restrict__ out) {
    __shared__ float As[16 * 132];
    __shared__ float Bs[16 * 128];

    const int K  = DD;
    const int NC = DD;
    const int rowBase = blockIdx.y * 128;
    const int colBase = blockIdx.x * 128;
    const int t  = threadIdx.x;
    const int ty = t >> 4;
    const int tx = t & 15;

    float acc[8][8];
#pragma unroll
    for (int i = 0; i < 8; i++)
#pragma unroll
        for (int j = 0; j < 8; j++) acc[i][j] = 0.f;

    for (int kt = 0; kt < K; kt += 16) {
#pragma unroll
        for (int it = 0; it < 2; it++) {
            int idx = it * 256 + t;
            int ra = idx >> 2;
            int ca = (idx & 3) << 2;
            float4 av = *(const float4*)&g_AO[(rowBase + ra) * K + kt + ca];
            As[(ca + 0) * 132 + ra] = av.x;
            As[(ca + 1) * 132 + ra] = av.y;
            As[(ca + 2) * 132 + ra] = av.z;
            As[(ca + 3) * 132 + ra] = av.w;
            int rb = idx >> 5;
            int cb = (idx & 31) << 2;
            *(float4*)&Bs[rb * 128 + cb] =
                *(const float4*)&W[(kt + rb) * NC + colBase + cb];
        }
        __syncthreads();

#pragma unroll
        for (int kk = 0; kk < 16; kk++) {
            float a[8], b[8];
            *(float4*)&a[0] = *(const float4*)&As[kk * 132 + ty * 8];
            *(float4*)&a[4] = *(const float4*)&As[kk * 132 + ty * 8 + 4];
            *(float4*)&b[0] = *(const float4*)&Bs[kk * 128 + tx * 8];
            *(float4*)&b[4] = *(const float4*)&Bs[kk * 128 + tx * 8 + 4];
#pragma unroll
            for (int i = 0; i < 8; i++)
#pragma unroll
                for (int j = 0; j < 8; j++) acc[i][j] += a[i] * b[j];
        }
        __syncthreads();
    }

    const int col = colBase + tx * 8;
    float4 bv0 = *(const float4*)&bias[col];
    float4 bv1 = *(const float4*)&bias[col + 4];
#pragma unroll
    for (int i = 0; i < 8; i++) {
        int m = rowBase + ty * 8 + i;
        float* p = &out[m * NC + col];
        *(float4*)(p)     = make_float4(acc[i][0] + bv0.x, acc[i][1] + bv0.y,
                                        acc[i][2] + bv0.z, acc[i][3] + bv0.w);
        *(float4*)(p + 4) = make_float4(acc[i][4] + bv1.x, acc[i][5] + bv1.y,
                                        acc[i][6] + bv1.z, acc[i][7] + bv1.w);
    }
}

// ---------------------------------------------------------------------------
extern "C" void kernel_launch(void* const* d_in, const int* in_sizes, int n_in,
                              void* d_out, int out_size) {
    const float* x     = (const float*)d_in[0];   // [4,2048,512]
    const float* w_qkv = (const float*)d_in[1];   // [512,1536]
    const float* w_out = (const float*)d_in[2];   // [512,512]
    const float* b_out = (const float*)d_in[3];   // [512]
    float* out = (float*)d_out;                   // [4,2048,512]

    qkv_gemm<<<dim3(12, 64), 256>>>(x, w_qkv);        // 1536/128 x 8192/128
    attn_kernel<<<dim3(64, 32), 256>>>();             // 2048/32 q-tiles x 32 bh
    out_gemm<<<dim3(4, 64), 256>>>(w_out, b_out, out);
}